// round 1
// baseline (speedup 1.0000x reference)
#include <cuda_runtime.h>
#include <math.h>

#define NN 512
#define SS 64
#define CC 1024
#define BB 10

// Scratch (allocation-free rule: device globals)
__device__ unsigned char g_counts[NN * CC];   // counts fit in u8 (<= 63)
__device__ float g_M[NN];                     // per-row max of counts
__device__ float g_Z[NN];                     // per-row sum exp(counts - M)

// ---------------------------------------------------------------------------
// Kernel 1: per-row histogram (drop last non-pad item), max and base partition
// 512 blocks x 256 threads. Tiny: ~3 us.
// ---------------------------------------------------------------------------
__global__ __launch_bounds__(256) void hist_kernel(const int* __restrict__ item_ids) {
    __shared__ int   hist[CC];
    __shared__ int   ids[SS];
    __shared__ int   s_last;
    __shared__ float red[256];

    const int n = blockIdx.x;
    const int tid = threadIdx.x;

    #pragma unroll
    for (int i = tid; i < CC; i += 256) hist[i] = 0;
    if (tid < SS) ids[tid] = item_ids[n * SS + tid];
    __syncthreads();

    if (tid == 0) {
        int last = -1;
        for (int s = SS - 1; s >= 0; --s) {
            if (ids[s] != 0) { last = s; break; }   // PAD == 0
        }
        s_last = last;   // -1 if all-pad row -> empty bincount
    }
    __syncthreads();

    if (tid < SS && ids[tid] != 0 && tid != s_last)
        atomicAdd(&hist[ids[tid]], 1);
    __syncthreads();

    // block max over counts
    float lmax = 0.0f;
    #pragma unroll
    for (int c = tid; c < CC; c += 256) lmax = fmaxf(lmax, (float)hist[c]);
    red[tid] = lmax;
    __syncthreads();
    for (int off = 128; off; off >>= 1) {
        if (tid < off) red[tid] = fmaxf(red[tid], red[tid + off]);
        __syncthreads();
    }
    const float M = red[0];
    __syncthreads();

    // store u8 counts + accumulate Z = sum exp(c - M)
    float lsum = 0.0f;
    #pragma unroll
    for (int c = tid; c < CC; c += 256) {
        const int h = hist[c];
        g_counts[n * CC + c] = (unsigned char)h;
        lsum += expf((float)h - M);
    }
    red[tid] = lsum;
    __syncthreads();
    for (int off = 128; off; off >>= 1) {
        if (tid < off) red[tid] += red[tid + off];
        __syncthreads();
    }
    if (tid == 0) { g_M[n] = M; g_Z[n] = red[0]; }
}

// ---------------------------------------------------------------------------
// Kernel 2: one block per (n,s). Rank-10 correction to the row partition,
// ban bitmask in shared, float4 streaming store. 32768 blocks x 256 threads.
// ---------------------------------------------------------------------------
__global__ __launch_bounds__(256) void pi_kernel(const int* __restrict__ ban_ids,
                                                 float* __restrict__ out) {
    __shared__ unsigned s_mask[CC / 32];
    __shared__ int      s_ban[BB];
    __shared__ float    s_corr[BB];
    __shared__ float    s_lse;

    const int blk = blockIdx.x;         // blk = n*SS + s
    const int n   = blk >> 6;           // SS == 64
    const int tid = threadIdx.x;
    const int c0  = tid * 4;

    // Issue the (latency-critical) counts load immediately — independent of
    // the ban/lse chain, so it overlaps the barriers below.
    const unsigned cw =
        *reinterpret_cast<const unsigned*>(&g_counts[n * CC + c0]);

    if (tid < CC / 32) s_mask[tid] = 0u;
    int myban = 0;
    if (tid < BB) { myban = ban_ids[blk * BB + tid]; s_ban[tid] = myban; }
    __syncthreads();

    if (tid < BB) {
        atomicOr(&s_mask[myban >> 5], 1u << (myban & 31));
        // dedupe: the scatter .set() applies once per distinct banned id
        bool dup = false;
        for (int j = 0; j < tid; ++j) dup |= (s_ban[j] == myban);
        s_corr[tid] = dup ? 0.0f
                          : expf((float)g_counts[n * CC + myban] - g_M[n]);
    }
    __syncthreads();

    if (tid == 0) {
        float corr = 0.0f;
        #pragma unroll
        for (int i = 0; i < BB; ++i) corr += s_corr[i];
        const float Z = fmaxf(g_Z[n] - corr, 1e-35f);
        s_lse = g_M[n] + logf(Z);
    }
    __syncthreads();

    const float    lse = s_lse;
    const unsigned m   = s_mask[c0 >> 5] >> (c0 & 31);

    float4 o;
    o.x = (float)( cw        & 0xffu) - lse - ((m & 1u) ? 1e9f : 0.0f);
    o.y = (float)((cw >>  8) & 0xffu) - lse - ((m & 2u) ? 1e9f : 0.0f);
    o.z = (float)((cw >> 16) & 0xffu) - lse - ((m & 4u) ? 1e9f : 0.0f);
    o.w = (float)( cw >> 24         ) - lse - ((m & 8u) ? 1e9f : 0.0f);

    reinterpret_cast<float4*>(out)[blk * (CC / 4) + tid] = o;
}

// ---------------------------------------------------------------------------
// Kernel 3: zero the v tail (output poisoned to 0xAA by the harness)
// ---------------------------------------------------------------------------
__global__ void zero_tail_kernel(float* __restrict__ out, int offset, int count) {
    const int i = blockIdx.x * blockDim.x + threadIdx.x;
    if (i < count) out[offset + i] = 0.0f;
}

extern "C" void kernel_launch(void* const* d_in, const int* in_sizes, int n_in,
                              void* d_out, int out_size) {
    // metadata order: null_w (f32, unused), ban_ids (i32 [N,S,B]), item_ids (i32 [N,S])
    const int* ban_ids  = (const int*)d_in[1];
    const int* item_ids = (const int*)d_in[2];
    float* out = (float*)d_out;

    hist_kernel<<<NN, 256>>>(item_ids);
    pi_kernel<<<NN * SS, 256>>>(ban_ids, out);

    const int pi_elems = NN * SS * CC;
    const int tail = out_size - pi_elems;   // v = zeros([N,S,1])
    if (tail > 0)
        zero_tail_kernel<<<(tail + 255) / 256, 256>>>(out, pi_elems, tail);
}

// round 2
// speedup vs baseline: 1.8533x; 1.8533x over previous
#include <cuda_runtime.h>
#include <math.h>

#define NN 512
#define SS 64
#define CC 1024
#define BB 10
#define PI_ELEMS (NN * SS * CC)

// ---------------------------------------------------------------------------
// Fused kernel: one block per row n. 512 blocks x 256 threads (one wave).
//   phase 1: in-block histogram of item_ids (drop last non-pad), PAD=0
//   phase 2: Z = sum_c exp(count[c])   (no max-shift: counts<=63, no overflow)
//   phase 3: lse[s] = log(Z - sum_{distinct banned} exp(count))  (threads 0..63)
//   phase 4: pure streaming store  out[n,s,c] = count[c] - lse[s]
//   phase 5: 640 scatter fixups    out[n,s,ban] = count[ban] - lse[s] - 1e9
//   phase 6: zero the v tail for this row
// ---------------------------------------------------------------------------
__global__ __launch_bounds__(256) void spop_fused_kernel(
    const int* __restrict__ ban_ids,
    const int* __restrict__ item_ids,
    float* __restrict__ out)
{
    __shared__ int   s_hist[CC];
    __shared__ int   s_ids[SS];
    __shared__ int   s_ban[SS * BB];
    __shared__ float s_lse[SS];
    __shared__ int   s_last;
    __shared__ float s_red[8];
    __shared__ float s_Z;

    const int n   = blockIdx.x;
    const int tid = threadIdx.x;
    const int lane = tid & 31;
    const int wrp  = tid >> 5;

    // ---- init + loads (all independent, issue early) ----
    #pragma unroll
    for (int i = tid; i < CC; i += 256) s_hist[i] = 0;
    if (tid < SS) s_ids[tid] = item_ids[n * SS + tid];
    // coalesced load of all 640 ban ids for this row
    #pragma unroll
    for (int i = tid; i < SS * BB; i += 256) s_ban[i] = ban_ids[n * SS * BB + i];
    if (tid == 0) s_last = -1;
    __syncthreads();

    // ---- last non-pad position (parallel atomicMax) ----
    if (tid < SS && s_ids[tid] != 0) atomicMax(&s_last, tid);
    __syncthreads();

    // ---- histogram (drop the last non-pad element) ----
    if (tid < SS && s_ids[tid] != 0 && tid != s_last)
        atomicAdd(&s_hist[s_ids[tid]], 1);
    __syncthreads();

    // ---- base values in registers + Z reduction ----
    const int c0 = tid * 4;
    const float b0 = (float)s_hist[c0 + 0];
    const float b1 = (float)s_hist[c0 + 1];
    const float b2 = (float)s_hist[c0 + 2];
    const float b3 = (float)s_hist[c0 + 3];

    float z = expf(b0) + expf(b1) + expf(b2) + expf(b3);
    #pragma unroll
    for (int off = 16; off; off >>= 1)
        z += __shfl_xor_sync(0xffffffffu, z, off);
    if (lane == 0) s_red[wrp] = z;
    __syncthreads();
    if (tid == 0) {
        float t = 0.0f;
        #pragma unroll
        for (int w = 0; w < 8; ++w) t += s_red[w];
        s_Z = t;
    }
    __syncthreads();

    // ---- per-s log-partition with rank-10 banned correction ----
    if (tid < SS) {
        const float Z = s_Z;
        float corr = 0.0f;
        int ids[BB];
        #pragma unroll
        for (int j = 0; j < BB; ++j) {
            const int id = s_ban[tid * BB + j];
            ids[j] = id;
            bool dup = false;
            #pragma unroll
            for (int k = 0; k < BB; ++k) if (k < j) dup |= (ids[k] == id);
            if (!dup) corr += expf((float)s_hist[id]);
        }
        s_lse[tid] = logf(fmaxf(Z - corr, 1e-35f));
    }
    __syncthreads();

    // ---- streaming store: 64 iterations of LDS + 4xFADD + STG.128 ----
    float4* __restrict__ out4 = reinterpret_cast<float4*>(out);
    const int rowbase = n * SS * (CC / 4);   // float4 index of (n, s=0, c=0)
    #pragma unroll 4
    for (int s = 0; s < SS; ++s) {
        const float l = s_lse[s];
        float4 o;
        o.x = b0 - l; o.y = b1 - l; o.z = b2 - l; o.w = b3 - l;
        out4[rowbase + s * (CC / 4) + tid] = o;
    }
    __syncthreads();   // order base stores before fixup overwrites

    // ---- scatter ban fixups: 640 idempotent 4B overwrites ----
    #pragma unroll
    for (int f = tid; f < SS * BB; f += 256) {
        const int s  = f / BB;
        const int id = s_ban[f];
        out[(n * SS + s) * CC + id] = (float)s_hist[id] - s_lse[s] - 1e9f;
    }

    // ---- v tail = zeros ----
    if (tid < SS) out[PI_ELEMS + n * SS + tid] = 0.0f;
}

extern "C" void kernel_launch(void* const* d_in, const int* in_sizes, int n_in,
                              void* d_out, int out_size) {
    // metadata order: null_w (f32, unused), ban_ids (i32 [N,S,B]), item_ids (i32 [N,S])
    const int* ban_ids  = (const int*)d_in[1];
    const int* item_ids = (const int*)d_in[2];
    float* out = (float*)d_out;

    spop_fused_kernel<<<NN, 256>>>(ban_ids, item_ids, out);
}

// round 3
// speedup vs baseline: 2.0145x; 1.0870x over previous
#include <cuda_runtime.h>
#include <math.h>

#define NN 512
#define SS 64
#define CC 1024
#define BB 10
#define SPLIT 2                    // CTAs per row
#define SLOC (SS / SPLIT)          // s-positions per CTA (32)
#define PI_ELEMS (NN * SS * CC)

// ---------------------------------------------------------------------------
// One CTA per (row, s-half). 1024 blocks x 256 threads (~7 CTAs/SM, occ ~85%).
// Histogram prologue duplicated per half (cheap); streaming store dominates.
// ---------------------------------------------------------------------------
__global__ __launch_bounds__(256) void spop_fused_kernel(
    const int* __restrict__ ban_ids,
    const int* __restrict__ item_ids,
    float* __restrict__ out)
{
    __shared__ int   s_hist[CC];
    __shared__ int   s_ids[SS];
    __shared__ int   s_ban[SLOC * BB];
    __shared__ float s_lse[SLOC];
    __shared__ int   s_last;
    __shared__ float s_red[8];
    __shared__ float s_Z;

    const int blk  = blockIdx.x;
    const int n    = blk >> 1;             // SPLIT == 2
    const int half = blk & 1;
    const int s0   = half * SLOC;
    const int tid  = threadIdx.x;
    const int lane = tid & 31;
    const int wrp  = tid >> 5;

    // ---- independent loads / init, all issued before first barrier ----
    #pragma unroll
    for (int i = tid; i < CC; i += 256) s_hist[i] = 0;
    if (tid < SS) s_ids[tid] = item_ids[n * SS + tid];
    #pragma unroll
    for (int i = tid; i < SLOC * BB; i += 256)
        s_ban[i] = ban_ids[(n * SS + s0) * BB + i];
    if (tid == 0) s_last = -1;
    __syncthreads();

    // ---- last non-pad position (PAD == 0) ----
    if (tid < SS && s_ids[tid] != 0) atomicMax(&s_last, tid);
    __syncthreads();

    // ---- histogram, dropping the last non-pad element ----
    if (tid < SS && s_ids[tid] != 0 && tid != s_last)
        atomicAdd(&s_hist[s_ids[tid]], 1);
    __syncthreads();

    // ---- base values to registers + Z = sum exp(count)  (counts<=63: safe) ----
    const int c0 = tid * 4;
    const float b0 = (float)s_hist[c0 + 0];
    const float b1 = (float)s_hist[c0 + 1];
    const float b2 = (float)s_hist[c0 + 2];
    const float b3 = (float)s_hist[c0 + 3];

    float z = expf(b0) + expf(b1) + expf(b2) + expf(b3);
    #pragma unroll
    for (int off = 16; off; off >>= 1)
        z += __shfl_xor_sync(0xffffffffu, z, off);
    if (lane == 0) s_red[wrp] = z;
    __syncthreads();
    if (tid == 0) {
        float t = 0.0f;
        #pragma unroll
        for (int w = 0; w < 8; ++w) t += s_red[w];
        s_Z = t;
    }
    __syncthreads();

    // ---- per-s log-partition with rank-10 distinct-banned correction ----
    if (tid < SLOC) {
        const float Z = s_Z;
        float corr = 0.0f;
        int ids[BB];
        #pragma unroll
        for (int j = 0; j < BB; ++j) {
            const int id = s_ban[tid * BB + j];
            ids[j] = id;
            bool dup = false;
            #pragma unroll
            for (int k = 0; k < BB; ++k) if (k < j) dup |= (ids[k] == id);
            if (!dup) corr += expf((float)s_hist[id]);
        }
        s_lse[tid] = logf(fmaxf(Z - corr, 1e-35f));
    }
    __syncthreads();

    // ---- streaming store: SLOC iterations of LDS-bcast + 4xFADD + STG.128 ----
    float4* __restrict__ out4 = reinterpret_cast<float4*>(out);
    const int base = (n * SS + s0) * (CC / 4);
    #pragma unroll 8
    for (int s = 0; s < SLOC; ++s) {
        const float l = s_lse[s];
        float4 o;
        o.x = b0 - l; o.y = b1 - l; o.z = b2 - l; o.w = b3 - l;
        out4[base + s * (CC / 4) + tid] = o;
    }
    __syncthreads();   // order base stores before scatter overwrites

    // ---- ban fixups: SLOC*BB idempotent 4B overwrites ----
    #pragma unroll
    for (int f = tid; f < SLOC * BB; f += 256) {
        const int s  = f / BB;
        const int id = s_ban[f];
        out[(n * SS + s0 + s) * CC + id] = (float)s_hist[id] - s_lse[s] - 1e9f;
    }

    // ---- v tail = zeros (first half-CTA of each row) ----
    if (half == 0 && tid < SS) out[PI_ELEMS + n * SS + tid] = 0.0f;
}

extern "C" void kernel_launch(void* const* d_in, const int* in_sizes, int n_in,
                              void* d_out, int out_size) {
    // metadata order: null_w (f32, unused), ban_ids (i32 [N,S,B]), item_ids (i32 [N,S])
    const int* ban_ids  = (const int*)d_in[1];
    const int* item_ids = (const int*)d_in[2];
    float* out = (float*)d_out;

    spop_fused_kernel<<<NN * SPLIT, 256>>>(ban_ids, item_ids, out);
}

// round 4
// speedup vs baseline: 2.1309x; 1.0578x over previous
#include <cuda_runtime.h>
#include <math.h>

#define NN 512
#define SS 64
#define CC 1024
#define BB 10
#define SB 4                        // s-positions per streaming CTA
#define PI_ELEMS (NN * SS * CC)

__device__ unsigned char g_counts[NN * CC];   // row histograms, u8 (<=63)
__device__ float         g_lse[NN * SS];      // per-(n,s) log-partition

// ---------------------------------------------------------------------------
// Kernel A: per-row hist + Z + all 64 lse. 512 CTAs x 256 threads.
// ---------------------------------------------------------------------------
__global__ __launch_bounds__(256) void row_stats_kernel(
    const int* __restrict__ ban_ids,
    const int* __restrict__ item_ids,
    float* __restrict__ out)
{
    __shared__ int   s_hist[CC];
    __shared__ int   s_ids[SS];
    __shared__ int   s_ban[SS * BB];
    __shared__ int   s_last;
    __shared__ float s_red[8];
    __shared__ float s_Z;

    const int n    = blockIdx.x;
    const int tid  = threadIdx.x;
    const int lane = tid & 31;
    const int wrp  = tid >> 5;

    #pragma unroll
    for (int i = tid; i < CC; i += 256) s_hist[i] = 0;
    if (tid < SS) s_ids[tid] = item_ids[n * SS + tid];
    #pragma unroll
    for (int i = tid; i < SS * BB; i += 256) s_ban[i] = ban_ids[n * SS * BB + i];
    if (tid == 0) s_last = -1;
    // v tail zeros (independent of everything)
    if (tid < SS) out[PI_ELEMS + n * SS + tid] = 0.0f;
    __syncthreads();

    if (tid < SS && s_ids[tid] != 0) atomicMax(&s_last, tid);   // PAD == 0
    __syncthreads();

    if (tid < SS && s_ids[tid] != 0 && tid != s_last)
        atomicAdd(&s_hist[s_ids[tid]], 1);
    __syncthreads();

    // pack 4 u8 counts + partial Z  (counts<=63: exp never overflows)
    const int c0 = tid * 4;
    const int h0 = s_hist[c0 + 0], h1 = s_hist[c0 + 1];
    const int h2 = s_hist[c0 + 2], h3 = s_hist[c0 + 3];
    reinterpret_cast<unsigned*>(g_counts)[n * (CC / 4) + tid] =
        (unsigned)h0 | ((unsigned)h1 << 8) | ((unsigned)h2 << 16) | ((unsigned)h3 << 24);

    float z = expf((float)h0) + expf((float)h1) + expf((float)h2) + expf((float)h3);
    #pragma unroll
    for (int off = 16; off; off >>= 1)
        z += __shfl_xor_sync(0xffffffffu, z, off);
    if (lane == 0) s_red[wrp] = z;
    __syncthreads();
    if (tid == 0) {
        float t = 0.0f;
        #pragma unroll
        for (int w = 0; w < 8; ++w) t += s_red[w];
        s_Z = t;
    }
    __syncthreads();

    // per-s log-partition with rank-10 distinct-banned correction
    if (tid < SS) {
        const float Z = s_Z;
        float corr = 0.0f;
        int ids[BB];
        #pragma unroll
        for (int j = 0; j < BB; ++j) {
            const int id = s_ban[tid * BB + j];
            ids[j] = id;
            bool dup = false;
            #pragma unroll
            for (int k = 0; k < BB; ++k) if (k < j) dup |= (ids[k] == id);
            if (!dup) corr += expf((float)s_hist[id]);
        }
        g_lse[n * SS + tid] = logf(fmaxf(Z - corr, 1e-35f));
    }
}

// ---------------------------------------------------------------------------
// Kernel B: pure streamer. 8192 CTAs x 256 threads, SB=4 s-positions each.
// Ban mask folded into the base store via shared bitmask -> single store pass.
// ---------------------------------------------------------------------------
__global__ __launch_bounds__(256) void stream_kernel(
    const int* __restrict__ ban_ids,
    float* __restrict__ out)
{
    __shared__ unsigned s_mask[SB][CC / 32];
    __shared__ float    s_l[SB];

    const int blk = blockIdx.x;
    const int n   = blk >> 4;                 // SS/SB == 16 chunks per row
    const int s0  = (blk & 15) * SB;
    const int tid = threadIdx.x;
    const int c0  = tid * 4;

    // issue the L2-hot counts load immediately (independent of mask chain)
    const unsigned cw =
        __ldg(&reinterpret_cast<const unsigned*>(g_counts)[n * (CC / 4) + tid]);

    if (tid < SB * (CC / 32))
        (&s_mask[0][0])[tid] = 0u;
    if (tid < SB) s_l[tid] = g_lse[n * SS + s0 + tid];
    int myban = 0;
    if (tid < SB * BB) myban = ban_ids[(n * SS + s0) * BB + tid];
    __syncthreads();

    if (tid < SB * BB)
        atomicOr(&s_mask[tid / BB][myban >> 5], 1u << (myban & 31));
    __syncthreads();

    const float f0 = (float)( cw        & 0xffu);
    const float f1 = (float)((cw >>  8) & 0xffu);
    const float f2 = (float)((cw >> 16) & 0xffu);
    const float f3 = (float)( cw >> 24         );

    float4* __restrict__ out4 = reinterpret_cast<float4*>(out);
    const int base = (n * SS + s0) * (CC / 4);
    #pragma unroll
    for (int s = 0; s < SB; ++s) {
        const float    l = s_l[s];
        const unsigned m = s_mask[s][c0 >> 5] >> (c0 & 31);
        float4 o;
        o.x = f0 - l - ((m & 1u) ? 1e9f : 0.0f);
        o.y = f1 - l - ((m & 2u) ? 1e9f : 0.0f);
        o.z = f2 - l - ((m & 4u) ? 1e9f : 0.0f);
        o.w = f3 - l - ((m & 8u) ? 1e9f : 0.0f);
        out4[base + s * (CC / 4) + tid] = o;
    }
}

extern "C" void kernel_launch(void* const* d_in, const int* in_sizes, int n_in,
                              void* d_out, int out_size) {
    // metadata order: null_w (f32, unused), ban_ids (i32 [N,S,B]), item_ids (i32 [N,S])
    const int* ban_ids  = (const int*)d_in[1];
    const int* item_ids = (const int*)d_in[2];
    float* out = (float*)d_out;

    row_stats_kernel<<<NN, 256>>>(ban_ids, item_ids, out);
    stream_kernel<<<NN * (SS / SB), 256>>>(ban_ids, out);
}